// round 13
// baseline (speedup 1.0000x reference)
#include <cuda_runtime.h>
#include <cuda_bf16.h>
#include <cstdint>
#include <cstddef>

// Problem constants (B=4, S=4096, H=16, D=64)
#define BSZ 4
#define SEQ 4096
#define NH 16
#define HD 64
#define CK 128
#define NC 32
#define BH 64
#define ROWSTRIDE 1024

// Inclusive per-chunk KV prefixes: [bh][n][64][64] fp32 (32 MB) + ready flags.
__device__ float g_kv[(size_t)BH * NC * HD * HD];
__device__ unsigned g_flag[BH * NC];

// ---------------------------------------------------------------------------
// PTX helpers (base sm_100-safe)
// ---------------------------------------------------------------------------
__device__ __forceinline__ uint32_t smem_u32(const void* p) {
    uint32_t a;
    asm("{ .reg .u64 t; cvta.to.shared.u64 t, %1; cvt.u32.u64 %0, t; }"
        : "=r"(a) : "l"(p));
    return a;
}
__device__ __forceinline__ void ldm4(uint32_t* r, uint32_t addr) {
    asm volatile("ldmatrix.sync.aligned.m8n8.x4.shared.b16 {%0,%1,%2,%3}, [%4];"
                 : "=r"(r[0]), "=r"(r[1]), "=r"(r[2]), "=r"(r[3]) : "r"(addr));
}
__device__ __forceinline__ void ldm4t(uint32_t* r, uint32_t addr) {
    asm volatile("ldmatrix.sync.aligned.m8n8.x4.trans.shared.b16 {%0,%1,%2,%3}, [%4];"
                 : "=r"(r[0]), "=r"(r[1]), "=r"(r[2]), "=r"(r[3]) : "r"(addr));
}
__device__ __forceinline__ void mma16816(float* c, const uint32_t* a, const uint32_t* b) {
    asm volatile(
        "mma.sync.aligned.m16n8k16.row.col.f32.bf16.bf16.f32 "
        "{%0,%1,%2,%3}, {%4,%5,%6,%7}, {%8,%9}, {%0,%1,%2,%3};"
        : "+f"(c[0]), "+f"(c[1]), "+f"(c[2]), "+f"(c[3])
        : "r"(a[0]), "r"(a[1]), "r"(a[2]), "r"(a[3]), "r"(b[0]), "r"(b[1]));
}

// swizzle for 128B rows ([*][64] bf16)
__device__ __forceinline__ uint32_t sw128(uint32_t x) { return x ^ ((x >> 3) & 0x70); }

// split fp32 -> (hi, lo) bf16
__device__ __forceinline__ void split1(float x, __nv_bfloat16& h, __nv_bfloat16& l) {
    h = __float2bfloat16(x);
    l = __float2bfloat16(x - __bfloat162float(h));
}
__device__ __forceinline__ void split2(float x0, float x1, uint32_t& hi, uint32_t& lo) {
    __nv_bfloat16 h0, l0, h1, l1;
    split1(x0, h0, l0);
    split1(x1, h1, l1);
    hi = (uint32_t)__bfloat16_as_ushort(h0) | ((uint32_t)__bfloat16_as_ushort(h1) << 16);
    lo = (uint32_t)__bfloat16_as_ushort(l0) | ((uint32_t)__bfloat16_as_ushort(l1) << 16);
}

// ---------------------------------------------------------------------------
// zero the chain flags (captured per replay, ordered before the fused kernel)
// ---------------------------------------------------------------------------
__global__ void zero_flags_kernel() {
    const int i = blockIdx.x * blockDim.x + threadIdx.x;
    if (i < BH * NC) g_flag[i] = 0u;
}

// ---------------------------------------------------------------------------
// Fused kernel: per 128-row chunk
//   KV_n = K^T V (published as inclusive prefix via deterministic per-bh chain)
//   O = tril(Q K^T) V + Q KV_prev   (strip-mined register-resident S)
// grid = 2048, blk = n*64 + bh (waits point only at earlier blocks),
// block = 256, smem 112 KB, 2 CTAs/SM.
// Phase order (latency hiding):
//   LDG Q -> regs | K,V convert->smem | sync | KV mma | chain publish |
//   Q convert->smem | sync | strips (fully unrolled, predicated) | Q·KV | out
// ---------------------------------------------------------------------------
#define O_QH 0
#define O_QL 16384
#define O_KH 32768
#define O_KL 49152
#define O_VH 65536
#define O_VL 81920
#define O_KVH 98304
#define O_KVL 106496
#define O_SMEM 114688

__global__ __launch_bounds__(256, 2) void fused_out_kernel(
    const float* __restrict__ qg, const float* __restrict__ kg,
    const float* __restrict__ vg, float* __restrict__ og) {
    extern __shared__ char sm[];
    const uint32_t smb = smem_u32(sm);

    const int tid = threadIdx.x, wid = tid >> 5, lane = tid & 31;
    const int blk = blockIdx.x;
    const int bh = blk & (BH - 1), n = blk >> 6;
    const int h = bh & (NH - 1), b = bh >> 4;
    const size_t base = ((size_t)b * SEQ + (size_t)n * CK) * ROWSTRIDE + (size_t)h * HD;

    const int la7 = lane & 7;
    const int la15 = lane & 15;
    const int gid = lane >> 2, t4 = lane & 3;

    // ---- phase 0: prefetch Q into registers (LDGs overlap K/V convert + KV mma)
    float2 qreg[16];
#pragma unroll
    for (int t = 0; t < 16; t++) {
        const int p = tid + t * 256;
        const int i = p >> 5, dp = p & 31;
        qreg[t] = *(const float2*)(qg + base + (size_t)i * ROWSTRIDE + 2 * dp);
    }

    // ---- phase 1: K, V load + split -> smem ----
#pragma unroll
    for (int t = 0; t < 16; t++) {
        const int p = tid + t * 256;
        const int i = p >> 5, dp = p & 31;
        const size_t g = base + (size_t)i * ROWSTRIDE + 2 * dp;
        float2 xk = *(const float2*)(kg + g);
        float2 xv = *(const float2*)(vg + g);
        uint32_t hh, ll;
        const uint32_t off = sw128((uint32_t)(i * 128 + dp * 4));
        split2(xk.x, xk.y, hh, ll);
        *(uint32_t*)(sm + O_KH + off) = hh;
        *(uint32_t*)(sm + O_KL + off) = ll;
        split2(xv.x, xv.y, hh, ll);
        *(uint32_t*)(sm + O_VH + off) = hh;
        *(uint32_t*)(sm + O_VL + off) = ll;
    }
    __syncthreads();

    // ---- phase 2: KV_n = K^T V (8 warps: wy2 = d block 16, wx2 = e block 32)
    const int wy2 = wid >> 1;
    const int wx2 = wid & 1;
    float kvacc[4][4];
#pragma unroll
    for (int f = 0; f < 4; f++)
#pragma unroll
        for (int c = 0; c < 4; c++) kvacc[f][c] = 0.f;

#pragma unroll 2
    for (int kb = 0; kb < 8; kb++) {
        const int k0 = kb * 16;
        uint32_t aH[4], aL[4];
        {
            const int row = k0 + ((lane >> 4) << 3) + la7;
            const int col = wy2 * 16 + ((lane >> 3) & 1) * 8;
            const uint32_t off = sw128((uint32_t)(row * 128 + col * 2));
            ldm4t(aH, smb + O_KH + off);
            ldm4t(aL, smb + O_KL + off);
        }
        uint32_t bH[2][4], bL[2][4];
#pragma unroll
        for (int nb = 0; nb < 2; nb++) {
            const int row = k0 + ((lane >> 3) & 1) * 8 + la7;
            const int col = wx2 * 32 + nb * 16 + ((lane >> 4) << 3);
            const uint32_t off = sw128((uint32_t)(row * 128 + col * 2));
            ldm4t(bH[nb], smb + O_VH + off);
            ldm4t(bL[nb], smb + O_VL + off);
        }
#pragma unroll
        for (int nb = 0; nb < 2; nb++)
#pragma unroll
            for (int f = 0; f < 2; f++) {
                float* c = kvacc[nb * 2 + f];
                mma16816(c, aH, &bH[nb][2 * f]);
                mma16816(c, aH, &bL[nb][2 * f]);
                mma16816(c, aL, &bH[nb][2 * f]);
            }
    }

    // ---- phase 3: chain — wait pred, read kv_prev, publish inclusive ----
    float* cur = g_kv + (size_t)(bh * NC + n) * (HD * HD);
    const float* prev = cur - (HD * HD);
    if (n > 0) {
        if (tid == 0) {
            unsigned* fp = g_flag + (bh * NC + n - 1);
            unsigned fv;
            do {
                asm volatile("ld.global.acquire.gpu.b32 %0, [%1];"
                             : "=r"(fv) : "l"(fp) : "memory");
                if (!fv) __nanosleep(64);
            } while (!fv);
        }
        __syncthreads();
    }
#pragma unroll
    for (int f = 0; f < 4; f++) {
        const int e0 = wx2 * 32 + f * 8 + 2 * t4;
        const int d0 = wy2 * 16 + gid;
        float2 p0 = make_float2(0.f, 0.f), p1 = make_float2(0.f, 0.f);
        if (n > 0) {
            p0 = *(const float2*)(prev + d0 * HD + e0);
            p1 = *(const float2*)(prev + (d0 + 8) * HD + e0);
        }
        *(float2*)(cur + d0 * HD + e0) =
            make_float2(p0.x + kvacc[f][0], p0.y + kvacc[f][1]);
        *(float2*)(cur + (d0 + 8) * HD + e0) =
            make_float2(p1.x + kvacc[f][2], p1.y + kvacc[f][3]);
        uint32_t hh, ll;
        split2(p0.x, p0.y, hh, ll);
        *(uint32_t*)(sm + O_KVH + sw128((uint32_t)(d0 * 128 + e0 * 2))) = hh;
        *(uint32_t*)(sm + O_KVL + sw128((uint32_t)(d0 * 128 + e0 * 2))) = ll;
        split2(p1.x, p1.y, hh, ll);
        *(uint32_t*)(sm + O_KVH + sw128((uint32_t)((d0 + 8) * 128 + e0 * 2))) = hh;
        *(uint32_t*)(sm + O_KVL + sw128((uint32_t)((d0 + 8) * 128 + e0 * 2))) = ll;
    }
    __threadfence();
    __syncthreads();
    if (tid == 0) {
        unsigned* fp = g_flag + (bh * NC + n);
        asm volatile("st.global.release.gpu.b32 [%0], %1;"
                     :: "l"(fp), "r"(1u) : "memory");
    }

    // ---- phase 4: Q convert -> smem (off the chain's critical path) ----
#pragma unroll
    for (int t = 0; t < 16; t++) {
        const int p = tid + t * 256;
        const int i = p >> 5, dp = p & 31;
        uint32_t hh, ll;
        const uint32_t off = sw128((uint32_t)(i * 128 + dp * 4));
        split2(qreg[t].x, qreg[t].y, hh, ll);
        *(uint32_t*)(sm + O_QH + off) = hh;
        *(uint32_t*)(sm + O_QL + off) = ll;
    }
    __syncthreads();

    // ---- resident Q A-fragments (loaded once) ----
    const int i0w = wid * 16;
    uint32_t aQH[4][4], aQL[4][4];
#pragma unroll
    for (int kb = 0; kb < 4; kb++) {
        const int row = i0w + la15;
        const int col = kb * 16 + ((lane >> 4) << 3);
        const uint32_t off = sw128((uint32_t)(row * 128 + col * 2));
        ldm4(aQH[kb], smb + O_QH + off);
        ldm4(aQL[kb], smb + O_QL + off);
    }

    float oacc[8][4];
#pragma unroll
    for (int nb = 0; nb < 8; nb++)
#pragma unroll
        for (int c = 0; c < 4; c++) oacc[nb][c] = 0.f;

    // ---- phase 5: causal strips, fully unrolled with warp-uniform guards ----
#pragma unroll
    for (int js = 0; js < 8; js++) {
        if (js <= wid) {
            const int j0 = js * 16;

            float sacc[2][4];
#pragma unroll
            for (int f = 0; f < 2; f++)
#pragma unroll
                for (int c = 0; c < 4; c++) sacc[f][c] = 0.f;

#pragma unroll
            for (int kb = 0; kb < 4; kb++) {
                uint32_t bH4[4], bL4[4];
                const int row = j0 + ((lane >> 4) << 3) + la7;
                const int col = kb * 16 + ((lane >> 3) & 1) * 8;
                const uint32_t off = sw128((uint32_t)(row * 128 + col * 2));
                ldm4(bH4, smb + O_KH + off);
                ldm4(bL4, smb + O_KL + off);
#pragma unroll
                for (int f = 0; f < 2; f++) {
                    float* c = sacc[f];
                    mma16816(c, aQH[kb], &bH4[2 * f]);
                    mma16816(c, aQH[kb], &bL4[2 * f]);
                    mma16816(c, aQL[kb], &bH4[2 * f]);
                }
            }

            uint32_t aSH[4], aSL[4];
#pragma unroll
            for (int nb = 0; nb < 2; nb++) {
                const int jj = j0 + nb * 8 + 2 * t4;
                const int iLo = i0w + gid, iHi = iLo + 8;
                const float x0 = (jj     <= iLo) ? sacc[nb][0] : 0.f;
                const float x1 = (jj + 1 <= iLo) ? sacc[nb][1] : 0.f;
                const float x2 = (jj     <= iHi) ? sacc[nb][2] : 0.f;
                const float x3 = (jj + 1 <= iHi) ? sacc[nb][3] : 0.f;
                uint32_t hi01, lo01, hi23, lo23;
                split2(x0, x1, hi01, lo01);
                split2(x2, x3, hi23, lo23);
                aSH[nb * 2] = hi01;  aSH[nb * 2 + 1] = hi23;
                aSL[nb * 2] = lo01;  aSL[nb * 2 + 1] = lo23;
            }

            {
                const int rowv = j0 + ((lane >> 3) & 1) * 8 + la7;
#pragma unroll
                for (int pe = 0; pe < 4; pe++) {
                    uint32_t vH4[4], vL4[4];
                    const int col = pe * 16 + ((lane >> 4) << 3);
                    const uint32_t off = sw128((uint32_t)(rowv * 128 + col * 2));
                    ldm4t(vH4, smb + O_VH + off);
                    ldm4t(vL4, smb + O_VL + off);
#pragma unroll
                    for (int f = 0; f < 2; f++) {
                        float* c = oacc[pe * 2 + f];
                        mma16816(c, aSH, &vH4[2 * f]);
                        mma16816(c, aSH, &vL4[2 * f]);
                        mma16816(c, aSL, &vH4[2 * f]);
                    }
                }
            }
        }
    }

    // ---- phase 6: O += Q KV_prev (resident aQ; KV from chain in smem) ----
#pragma unroll
    for (int kb = 0; kb < 4; kb++) {
        const int rowkv = kb * 16 + ((lane >> 3) & 1) * 8 + la7;
#pragma unroll
        for (int pe = 0; pe < 4; pe++) {
            uint32_t bH4[4], bL4[4];
            const int col = pe * 16 + ((lane >> 4) << 3);
            const uint32_t off = sw128((uint32_t)(rowkv * 128 + col * 2));
            ldm4t(bH4, smb + O_KVH + off);
            ldm4t(bL4, smb + O_KVL + off);
#pragma unroll
            for (int f = 0; f < 2; f++) {
                float* c = oacc[pe * 2 + f];
                mma16816(c, aQH[kb], &bH4[2 * f]);
                mma16816(c, aQH[kb], &bL4[2 * f]);
                mma16816(c, aQL[kb], &bH4[2 * f]);
            }
        }
    }

    // ---- epilogue ----
#pragma unroll
    for (int nb = 0; nb < 8; nb++) {
        const int e0 = nb * 8 + 2 * t4;
        const int i0 = i0w + gid;
        *(float2*)(og + base + (size_t)i0 * ROWSTRIDE + e0) =
            make_float2(oacc[nb][0], oacc[nb][1]);
        *(float2*)(og + base + (size_t)(i0 + 8) * ROWSTRIDE + e0) =
            make_float2(oacc[nb][2], oacc[nb][3]);
    }
}

// ---------------------------------------------------------------------------
// kernel_launch: zero flags, then the fused kernel (both graph-capturable)
// ---------------------------------------------------------------------------
extern "C" void kernel_launch(void* const* d_in, const int* in_sizes, int n_in,
                              void* d_out, int out_size) {
    (void)in_sizes; (void)n_in; (void)out_size;
    const float* q = (const float*)d_in[0];
    const float* k = (const float*)d_in[1];
    const float* v = (const float*)d_in[2];
    float* out = (float*)d_out;

    zero_flags_kernel<<<(BH * NC + 255) / 256, 256>>>();

    cudaFuncSetAttribute(fused_out_kernel, cudaFuncAttributeMaxDynamicSharedMemorySize,
                         O_SMEM);
    fused_out_kernel<<<BH * NC, 256, O_SMEM>>>(q, k, v, out);
}

// round 14
// speedup vs baseline: 1.0298x; 1.0298x over previous
#include <cuda_runtime.h>
#include <cuda_bf16.h>
#include <cstdint>
#include <cstddef>

// Problem constants (B=4, S=4096, H=16, D=64)
#define BSZ 4
#define SEQ 4096
#define NH 16
#define HD 64
#define CK 128
#define NC 32
#define BH 64
#define ROWSTRIDE 1024

// Inclusive per-chunk KV prefixes: [bh][n][64][64] fp32 (32 MB) + ready flags.
__device__ float g_kv[(size_t)BH * NC * HD * HD];
__device__ unsigned g_flag[BH * NC];

// ---------------------------------------------------------------------------
// PTX helpers (base sm_100-safe)
// ---------------------------------------------------------------------------
__device__ __forceinline__ uint32_t smem_u32(const void* p) {
    uint32_t a;
    asm("{ .reg .u64 t; cvta.to.shared.u64 t, %1; cvt.u32.u64 %0, t; }"
        : "=r"(a) : "l"(p));
    return a;
}
__device__ __forceinline__ void ldm4(uint32_t* r, uint32_t addr) {
    asm volatile("ldmatrix.sync.aligned.m8n8.x4.shared.b16 {%0,%1,%2,%3}, [%4];"
                 : "=r"(r[0]), "=r"(r[1]), "=r"(r[2]), "=r"(r[3]) : "r"(addr));
}
__device__ __forceinline__ void ldm4t(uint32_t* r, uint32_t addr) {
    asm volatile("ldmatrix.sync.aligned.m8n8.x4.trans.shared.b16 {%0,%1,%2,%3}, [%4];"
                 : "=r"(r[0]), "=r"(r[1]), "=r"(r[2]), "=r"(r[3]) : "r"(addr));
}
__device__ __forceinline__ void mma16816(float* c, const uint32_t* a, const uint32_t* b) {
    asm volatile(
        "mma.sync.aligned.m16n8k16.row.col.f32.bf16.bf16.f32 "
        "{%0,%1,%2,%3}, {%4,%5,%6,%7}, {%8,%9}, {%0,%1,%2,%3};"
        : "+f"(c[0]), "+f"(c[1]), "+f"(c[2]), "+f"(c[3])
        : "r"(a[0]), "r"(a[1]), "r"(a[2]), "r"(a[3]), "r"(b[0]), "r"(b[1]));
}

// swizzle for 128B rows ([*][64] bf16)
__device__ __forceinline__ uint32_t sw128(uint32_t x) { return x ^ ((x >> 3) & 0x70); }

// split fp32 -> (hi, lo) bf16
__device__ __forceinline__ void split1(float x, __nv_bfloat16& h, __nv_bfloat16& l) {
    h = __float2bfloat16(x);
    l = __float2bfloat16(x - __bfloat162float(h));
}
__device__ __forceinline__ void split2(float x0, float x1, uint32_t& hi, uint32_t& lo) {
    __nv_bfloat16 h0, l0, h1, l1;
    split1(x0, h0, l0);
    split1(x1, h1, l1);
    hi = (uint32_t)__bfloat16_as_ushort(h0) | ((uint32_t)__bfloat16_as_ushort(h1) << 16);
    lo = (uint32_t)__bfloat16_as_ushort(l0) | ((uint32_t)__bfloat16_as_ushort(l1) << 16);
}

// ---------------------------------------------------------------------------
// zero the chain flags (captured per replay, ordered before the fused kernel)
// ---------------------------------------------------------------------------
__global__ void zero_flags_kernel() {
    const int i = blockIdx.x * blockDim.x + threadIdx.x;
    if (i < BH * NC) g_flag[i] = 0u;
}

// ---------------------------------------------------------------------------
// Fused kernel: per 128-row chunk
//   KV_n = K^T V (published as inclusive prefix via deterministic per-bh chain)
//   O = tril(Q K^T) V + Q KV_prev   (strip-mined register-resident S)
// grid = 2048, blk = n*64 + bh (waits point only at earlier blocks),
// block = 256, smem 112 KB, 2 CTAs/SM.
// SMSP balance: warp wid owns i-block ib = (wid<4) ? wid : 11-wid, so each
// SM-subpartition (wid%4) hosts i-blocks summing to 9 strip-units.
// ---------------------------------------------------------------------------
#define O_QH 0
#define O_QL 16384
#define O_KH 32768
#define O_KL 49152
#define O_VH 65536
#define O_VL 81920
#define O_KVH 98304
#define O_KVL 106496
#define O_SMEM 114688

__global__ __launch_bounds__(256, 2) void fused_out_kernel(
    const float* __restrict__ qg, const float* __restrict__ kg,
    const float* __restrict__ vg, float* __restrict__ og) {
    extern __shared__ char sm[];
    const uint32_t smb = smem_u32(sm);

    const int tid = threadIdx.x, wid = tid >> 5, lane = tid & 31;
    const int blk = blockIdx.x;
    const int bh = blk & (BH - 1), n = blk >> 6;
    const int h = bh & (NH - 1), b = bh >> 4;
    const size_t base = ((size_t)b * SEQ + (size_t)n * CK) * ROWSTRIDE + (size_t)h * HD;

    const int la7 = lane & 7;
    const int la15 = lane & 15;
    const int gid = lane >> 2, t4 = lane & 3;

    // ---- load + split: Q, K, V (float2 path) ----
#pragma unroll
    for (int p = tid; p < 4096; p += 256) {
        const int i = p >> 5, dp = p & 31;
        const size_t g = base + (size_t)i * ROWSTRIDE + 2 * dp;
        float2 xq = *(const float2*)(qg + g);
        float2 xk = *(const float2*)(kg + g);
        float2 xv = *(const float2*)(vg + g);
        uint32_t hh, ll;
        const uint32_t off = sw128((uint32_t)(i * 128 + dp * 4));
        split2(xq.x, xq.y, hh, ll);
        *(uint32_t*)(sm + O_QH + off) = hh;
        *(uint32_t*)(sm + O_QL + off) = ll;
        split2(xk.x, xk.y, hh, ll);
        *(uint32_t*)(sm + O_KH + off) = hh;
        *(uint32_t*)(sm + O_KL + off) = ll;
        split2(xv.x, xv.y, hh, ll);
        *(uint32_t*)(sm + O_VH + off) = hh;
        *(uint32_t*)(sm + O_VL + off) = ll;
    }
    __syncthreads();

    // ---- KV_n = K^T V  (8 warps: wy2 = d block of 16, wx2 = e block of 32) ----
    const int wy2 = wid >> 1;
    const int wx2 = wid & 1;
    float kvacc[4][4];
#pragma unroll
    for (int f = 0; f < 4; f++)
#pragma unroll
        for (int c = 0; c < 4; c++) kvacc[f][c] = 0.f;

#pragma unroll 2
    for (int kb = 0; kb < 8; kb++) {
        const int k0 = kb * 16;
        uint32_t aH[4], aL[4];
        {
            const int row = k0 + ((lane >> 4) << 3) + la7;
            const int col = wy2 * 16 + ((lane >> 3) & 1) * 8;
            const uint32_t off = sw128((uint32_t)(row * 128 + col * 2));
            ldm4t(aH, smb + O_KH + off);
            ldm4t(aL, smb + O_KL + off);
        }
        uint32_t bH[2][4], bL[2][4];
#pragma unroll
        for (int nb = 0; nb < 2; nb++) {
            const int row = k0 + ((lane >> 3) & 1) * 8 + la7;
            const int col = wx2 * 32 + nb * 16 + ((lane >> 4) << 3);
            const uint32_t off = sw128((uint32_t)(row * 128 + col * 2));
            ldm4t(bH[nb], smb + O_VH + off);
            ldm4t(bL[nb], smb + O_VL + off);
        }
#pragma unroll
        for (int nb = 0; nb < 2; nb++)
#pragma unroll
            for (int f = 0; f < 2; f++) {
                float* c = kvacc[nb * 2 + f];
                mma16816(c, aH, &bH[nb][2 * f]);
                mma16816(c, aH, &bL[nb][2 * f]);
                mma16816(c, aL, &bH[nb][2 * f]);
            }
    }

    // ---- chain: wait pred inclusive, read kv_prev, publish own inclusive ----
    float* cur = g_kv + (size_t)(bh * NC + n) * (HD * HD);
    const float* prev = cur - (HD * HD);
    if (n > 0) {
        if (tid == 0) {
            unsigned* fp = g_flag + (bh * NC + n - 1);
            unsigned fv;
            do {
                asm volatile("ld.global.acquire.gpu.b32 %0, [%1];"
                             : "=r"(fv) : "l"(fp) : "memory");
                if (!fv) __nanosleep(64);
            } while (!fv);
        }
        __syncthreads();
    }
#pragma unroll
    for (int f = 0; f < 4; f++) {
        const int e0 = wx2 * 32 + f * 8 + 2 * t4;
        const int d0 = wy2 * 16 + gid;
        float2 p0 = make_float2(0.f, 0.f), p1 = make_float2(0.f, 0.f);
        if (n > 0) {
            p0 = *(const float2*)(prev + d0 * HD + e0);
            p1 = *(const float2*)(prev + (d0 + 8) * HD + e0);
        }
        *(float2*)(cur + d0 * HD + e0) =
            make_float2(p0.x + kvacc[f][0], p0.y + kvacc[f][1]);
        *(float2*)(cur + (d0 + 8) * HD + e0) =
            make_float2(p1.x + kvacc[f][2], p1.y + kvacc[f][3]);
        uint32_t hh, ll;
        split2(p0.x, p0.y, hh, ll);
        *(uint32_t*)(sm + O_KVH + sw128((uint32_t)(d0 * 128 + e0 * 2))) = hh;
        *(uint32_t*)(sm + O_KVL + sw128((uint32_t)(d0 * 128 + e0 * 2))) = ll;
        split2(p1.x, p1.y, hh, ll);
        *(uint32_t*)(sm + O_KVH + sw128((uint32_t)((d0 + 8) * 128 + e0 * 2))) = hh;
        *(uint32_t*)(sm + O_KVL + sw128((uint32_t)((d0 + 8) * 128 + e0 * 2))) = ll;
    }
    __threadfence();
    __syncthreads();
    if (tid == 0) {
        unsigned* fp = g_flag + (bh * NC + n);
        asm volatile("st.global.release.gpu.b32 [%0], %1;"
                     :: "l"(fp), "r"(1u) : "memory");
    }

    // ---- SMSP-balanced i-block: wid%4 pairs sum to 9 strip-units ----
    const int ib = (wid < 4) ? wid : 11 - wid;   // {0,1,2,3,7,6,5,4}
    const int i0w = ib * 16;

    // ---- resident Q A-fragments (loaded once) ----
    uint32_t aQH[4][4], aQL[4][4];
#pragma unroll
    for (int kb = 0; kb < 4; kb++) {
        const int row = i0w + la15;
        const int col = kb * 16 + ((lane >> 4) << 3);
        const uint32_t off = sw128((uint32_t)(row * 128 + col * 2));
        ldm4(aQH[kb], smb + O_QH + off);
        ldm4(aQL[kb], smb + O_QL + off);
    }

    float oacc[8][4];
#pragma unroll
    for (int nb = 0; nb < 8; nb++)
#pragma unroll
        for (int c = 0; c < 4; c++) oacc[nb][c] = 0.f;

    // ---- causal strips: S strip (regs) -> split -> S·V ----
    for (int js = 0; js <= ib; js++) {
        const int j0 = js * 16;

        float sacc[2][4];
#pragma unroll
        for (int f = 0; f < 2; f++)
#pragma unroll
            for (int c = 0; c < 4; c++) sacc[f][c] = 0.f;

#pragma unroll
        for (int kb = 0; kb < 4; kb++) {
            uint32_t bH4[4], bL4[4];
            const int row = j0 + ((lane >> 4) << 3) + la7;
            const int col = kb * 16 + ((lane >> 3) & 1) * 8;
            const uint32_t off = sw128((uint32_t)(row * 128 + col * 2));
            ldm4(bH4, smb + O_KH + off);
            ldm4(bL4, smb + O_KL + off);
#pragma unroll
            for (int f = 0; f < 2; f++) {
                float* c = sacc[f];
                mma16816(c, aQH[kb], &bH4[2 * f]);
                mma16816(c, aQH[kb], &bL4[2 * f]);
                mma16816(c, aQL[kb], &bH4[2 * f]);
            }
        }

        uint32_t aSH[4], aSL[4];
#pragma unroll
        for (int nb = 0; nb < 2; nb++) {
            const int jj = j0 + nb * 8 + 2 * t4;
            const int iLo = i0w + gid, iHi = iLo + 8;
            const float x0 = (jj     <= iLo) ? sacc[nb][0] : 0.f;
            const float x1 = (jj + 1 <= iLo) ? sacc[nb][1] : 0.f;
            const float x2 = (jj     <= iHi) ? sacc[nb][2] : 0.f;
            const float x3 = (jj + 1 <= iHi) ? sacc[nb][3] : 0.f;
            uint32_t hi01, lo01, hi23, lo23;
            split2(x0, x1, hi01, lo01);
            split2(x2, x3, hi23, lo23);
            aSH[nb * 2] = hi01;  aSH[nb * 2 + 1] = hi23;
            aSL[nb * 2] = lo01;  aSL[nb * 2 + 1] = lo23;
        }

        {
            const int rowv = j0 + ((lane >> 3) & 1) * 8 + la7;
#pragma unroll
            for (int pe = 0; pe < 4; pe++) {
                uint32_t vH4[4], vL4[4];
                const int col = pe * 16 + ((lane >> 4) << 3);
                const uint32_t off = sw128((uint32_t)(rowv * 128 + col * 2));
                ldm4t(vH4, smb + O_VH + off);
                ldm4t(vL4, smb + O_VL + off);
#pragma unroll
                for (int f = 0; f < 2; f++) {
                    float* c = oacc[pe * 2 + f];
                    mma16816(c, aSH, &vH4[2 * f]);
                    mma16816(c, aSH, &vL4[2 * f]);
                    mma16816(c, aSL, &vH4[2 * f]);
                }
            }
        }
    }

    // ---- O += Q KV_prev (resident aQ; KV from chain in smem) ----
#pragma unroll
    for (int kb = 0; kb < 4; kb++) {
        const int rowkv = kb * 16 + ((lane >> 3) & 1) * 8 + la7;
#pragma unroll
        for (int pe = 0; pe < 4; pe++) {
            uint32_t bH4[4], bL4[4];
            const int col = pe * 16 + ((lane >> 4) << 3);
            const uint32_t off = sw128((uint32_t)(rowkv * 128 + col * 2));
            ldm4t(bH4, smb + O_KVH + off);
            ldm4t(bL4, smb + O_KVL + off);
#pragma unroll
            for (int f = 0; f < 2; f++) {
                float* c = oacc[pe * 2 + f];
                mma16816(c, aQH[kb], &bH4[2 * f]);
                mma16816(c, aQH[kb], &bL4[2 * f]);
                mma16816(c, aQL[kb], &bH4[2 * f]);
            }
        }
    }

    // ---- epilogue ----
#pragma unroll
    for (int nb = 0; nb < 8; nb++) {
        const int e0 = nb * 8 + 2 * t4;
        const int i0 = i0w + gid;
        *(float2*)(og + base + (size_t)i0 * ROWSTRIDE + e0) =
            make_float2(oacc[nb][0], oacc[nb][1]);
        *(float2*)(og + base + (size_t)(i0 + 8) * ROWSTRIDE + e0) =
            make_float2(oacc[nb][2], oacc[nb][3]);
    }
}

// ---------------------------------------------------------------------------
// kernel_launch: zero flags, then the fused kernel (both graph-capturable)
// ---------------------------------------------------------------------------
extern "C" void kernel_launch(void* const* d_in, const int* in_sizes, int n_in,
                              void* d_out, int out_size) {
    (void)in_sizes; (void)n_in; (void)out_size;
    const float* q = (const float*)d_in[0];
    const float* k = (const float*)d_in[1];
    const float* v = (const float*)d_in[2];
    float* out = (float*)d_out;

    zero_flags_kernel<<<(BH * NC + 255) / 256, 256>>>();

    cudaFuncSetAttribute(fused_out_kernel, cudaFuncAttributeMaxDynamicSharedMemorySize,
                         O_SMEM);
    fused_out_kernel<<<BH * NC, 256, O_SMEM>>>(q, k, v, out);
}